// round 1
// baseline (speedup 1.0000x reference)
#include <cuda_runtime.h>
#include <math.h>

#define N_NODES 50000
#define KN 32
#define D 128
#define TBL 2048

// Precomputed per-launch scratch (device globals: no allocation allowed)
__device__ float g_u1[D];      // W1 @ W4
__device__ float g_u2[D];      // W2 @ W4
__device__ float g_tbl[TBL];   // c(x) = sum_e sigmoid(x*W3[e])*W4[e], x in [0,1]

// ---------------------------------------------------------------------------
// Precompute kernel: u1, u2 and the dt->scalar table.
// Block 0: u1/u2 (thread d = one row dot). Blocks 1..16: table entries.
// ---------------------------------------------------------------------------
__global__ void precompute_kernel(const float* __restrict__ W1,
                                  const float* __restrict__ W2,
                                  const float* __restrict__ W3,
                                  const float* __restrict__ W4) {
    int b = blockIdx.x;
    int t = threadIdx.x;
    if (b == 0) {
        float s1 = 0.0f, s2 = 0.0f;
        #pragma unroll 4
        for (int e = 0; e < D; e++) {
            float w4 = W4[e];
            s1 = fmaf(W1[t * D + e], w4, s1);
            s2 = fmaf(W2[t * D + e], w4, s2);
        }
        g_u1[t] = s1;
        g_u2[t] = s2;
    } else {
        int j = (b - 1) * blockDim.x + t;
        if (j < TBL) {
            float x = (float)j * (1.0f / (float)(TBL - 1));
            float s = 0.0f;
            for (int e = 0; e < D; e++) {
                float z = x * W3[e];
                float sig = 1.0f / (1.0f + expf(-z));
                s = fmaf(sig, W4[e], s);
            }
            g_tbl[j] = s;
        }
    }
}

// ---------------------------------------------------------------------------
// Main kernel: one block (128 threads) per node.
//   score[k] = relu(a + neigh[k]·u2 + c(dt[k]) + b4), softmax over k,
//   out = sum_k w[k] * neigh[k]
// ---------------------------------------------------------------------------
__global__ __launch_bounds__(128) void attn_agg_kernel(
    const float* __restrict__ self_vecs,   // [N, D]
    const float* __restrict__ neigh,       // [N, K, D]
    const float* __restrict__ dt,          // [N, K]
    const float* __restrict__ b4,          // [1]
    float* __restrict__ out,               // [N, D]
    float* __restrict__ score_out)         // [N, K]
{
    const int n = blockIdx.x;
    const int t = threadIdx.x;
    const int warp = t >> 5;
    const int lane = t & 31;

    __shared__ float tile[KN * D];   // 16 KB neighbor tile
    __shared__ float sc[KN];
    __shared__ float red[4];
    __shared__ float a_sh;

    // ---- Load neighbor tile (coalesced float4, 8 per thread) --------------
    const float4* __restrict__ src =
        reinterpret_cast<const float4*>(neigh + (size_t)n * KN * D);
    float4* dst = reinterpret_cast<float4*>(tile);
    #pragma unroll
    for (int i = 0; i < 8; i++) {
        dst[i * 128 + t] = src[i * 128 + t];
    }

    // ---- a = self_vec · u1 (block reduce) ----------------------------------
    float ap = self_vecs[(size_t)n * D + t] * g_u1[t];
    #pragma unroll
    for (int o = 16; o; o >>= 1) ap += __shfl_xor_sync(0xffffffffu, ap, o);
    if (lane == 0) red[warp] = ap;
    __syncthreads();                       // tile + red visible
    if (t == 0) a_sh = red[0] + red[1] + red[2] + red[3];
    __syncthreads();

    const float a    = a_sh;
    const float bias = b4[0];

    // Per-lane chunk of u2 (16B aligned: lane*4 floats)
    const float4 u2v = *reinterpret_cast<const float4*>(&g_u2[lane * 4]);

    // ---- Scores: warp w handles neighbors [8w, 8w+8) -----------------------
    const float tscale = (float)(TBL - 1);
    #pragma unroll
    for (int kk = 0; kk < 8; kk++) {
        int k = warp * 8 + kk;
        float4 v = *reinterpret_cast<const float4*>(&tile[k * D + lane * 4]);
        float p = v.x * u2v.x + v.y * u2v.y + v.z * u2v.z + v.w * u2v.w;
        #pragma unroll
        for (int o = 16; o; o >>= 1) p += __shfl_xor_sync(0xffffffffu, p, o);
        if (lane == 0) {
            float x = dt[(size_t)n * KN + k];
            x = fminf(fmaxf(x, 0.0f), 1.0f);
            float xf = x * tscale;
            int   i0 = (int)xf;
            if (i0 > TBL - 2) i0 = TBL - 2;
            float f  = xf - (float)i0;
            float c  = g_tbl[i0] + f * (g_tbl[i0 + 1] - g_tbl[i0]);
            float s  = a + p + c + bias;
            sc[k] = fmaxf(s, 0.0f);        // relu
        }
    }
    __syncthreads();

    // ---- Softmax over K=32 (warp 0) ----------------------------------------
    if (warp == 0) {
        float s = sc[lane];
        float m = s;
        #pragma unroll
        for (int o = 16; o; o >>= 1)
            m = fmaxf(m, __shfl_xor_sync(0xffffffffu, m, o));
        float e = expf(s - m);
        float sum = e;
        #pragma unroll
        for (int o = 16; o; o >>= 1) sum += __shfl_xor_sync(0xffffffffu, sum, o);
        float w = e / sum;
        sc[lane] = w;
        score_out[(size_t)n * KN + lane] = w;
    }
    __syncthreads();

    // ---- Weighted neighbor sum: out[d] = sum_k w[k]*tile[k][d] -------------
    float acc = 0.0f;
    #pragma unroll
    for (int k = 0; k < KN; k++) {
        acc = fmaf(sc[k], tile[k * D + t], acc);
    }
    out[(size_t)n * D + t] = acc;
}

// ---------------------------------------------------------------------------
// Launch
// ---------------------------------------------------------------------------
extern "C" void kernel_launch(void* const* d_in, const int* in_sizes, int n_in,
                              void* d_out, int out_size) {
    const float* self_vecs = (const float*)d_in[0];  // [N, 128]
    const float* neigh     = (const float*)d_in[1];  // [N, 32, 128]
    const float* dt        = (const float*)d_in[2];  // [N, 32]
    const float* W1        = (const float*)d_in[3];  // [128, 128]
    const float* W2        = (const float*)d_in[4];  // [128, 128]
    const float* W3        = (const float*)d_in[5];  // [1, 128]
    const float* W4        = (const float*)d_in[6];  // [128, 1]
    const float* b4        = (const float*)d_in[7];  // [1]

    float* out   = (float*)d_out;                      // [N, 128] first
    float* score = out + (size_t)N_NODES * D;          // then [N, 32]

    precompute_kernel<<<1 + TBL / 128, 128>>>(W1, W2, W3, W4);
    attn_agg_kernel<<<N_NODES, 128>>>(self_vecs, neigh, dt, b4, out, score);
}

// round 3
// speedup vs baseline: 1.4514x; 1.4514x over previous
#include <cuda_runtime.h>
#include <math.h>

#define N_NODES 50000
#define KN 32
#define D 128
#define TBL 2048

__device__ __align__(16) float g_u1[D];    // W1 @ W4
__device__ __align__(16) float g_u2[D];    // W2 @ W4
__device__ float g_tbl[TBL];               // c(x) = sum_e sigmoid(x*W3[e])*W4[e]

// ---------------------------------------------------------------------------
// Precompute kernel: u1, u2 and the dt->scalar table.
// ---------------------------------------------------------------------------
__global__ void precompute_kernel(const float* __restrict__ W1,
                                  const float* __restrict__ W2,
                                  const float* __restrict__ W3,
                                  const float* __restrict__ W4) {
    int b = blockIdx.x;
    int t = threadIdx.x;
    if (b == 0) {
        float s1 = 0.0f, s2 = 0.0f;
        #pragma unroll 4
        for (int e = 0; e < D; e++) {
            float w4 = W4[e];
            s1 = fmaf(W1[t * D + e], w4, s1);
            s2 = fmaf(W2[t * D + e], w4, s2);
        }
        g_u1[t] = s1;
        g_u2[t] = s2;
    } else {
        int j = (b - 1) * blockDim.x + t;
        if (j < TBL) {
            float x = (float)j * (1.0f / (float)(TBL - 1));
            float s = 0.0f;
            for (int e = 0; e < D; e++) {
                float z = x * W3[e];
                float sig = 1.0f / (1.0f + expf(-z));
                s = fmaf(sig, W4[e], s);
            }
            g_tbl[j] = s;
        }
    }
}

// ---------------------------------------------------------------------------
// Main kernel: one block (128 threads) per node. Neighbor tile lives in
// REGISTERS: warp w owns rows [8w, 8w+8), lane l owns columns [4l, 4l+4).
// ---------------------------------------------------------------------------
__global__ __launch_bounds__(128) void attn_agg_kernel(
    const float* __restrict__ self_vecs,   // [N, D]
    const float* __restrict__ neigh,       // [N, K, D]
    const float* __restrict__ dt,          // [N, K]
    const float* __restrict__ b4,          // [1]
    float* __restrict__ out,               // [N, D]
    float* __restrict__ score_out)         // [N, K]
{
    const int n = blockIdx.x;
    const int t = threadIdx.x;
    const int warp = t >> 5;
    const int lane = t & 31;

    __shared__ __align__(16) float partial[4][D];  // cross-warp partials (first: aligned)
    __shared__ float sc[KN];                       // scores / weights
    __shared__ float red[4];                       // self-dot partials
    __shared__ float a_sh;

    // ---- Load 8 neighbor rows into registers (coalesced float4, streaming) --
    const float4* __restrict__ base =
        reinterpret_cast<const float4*>(neigh + (size_t)n * KN * D) +
        warp * (8 * 32) + lane;
    float4 v[8];
    #pragma unroll
    for (int kk = 0; kk < 8; kk++) {
        v[kk] = __ldcs(base + kk * 32);
    }

    // ---- a = self_vec · u1 (block reduce) ----------------------------------
    float ap = self_vecs[(size_t)n * D + t] * g_u1[t];
    #pragma unroll
    for (int o = 16; o; o >>= 1) ap += __shfl_xor_sync(0xffffffffu, ap, o);
    if (lane == 0) red[warp] = ap;
    __syncthreads();
    if (t == 0) a_sh = red[0] + red[1] + red[2] + red[3];
    __syncthreads();

    const float a    = a_sh;
    const float bias = b4[0];
    const float4 u2v = *reinterpret_cast<const float4*>(&g_u2[lane * 4]);

    // ---- Scores from registers ---------------------------------------------
    const float tscale = (float)(TBL - 1);
    #pragma unroll
    for (int kk = 0; kk < 8; kk++) {
        float p = v[kk].x * u2v.x + v[kk].y * u2v.y +
                  v[kk].z * u2v.z + v[kk].w * u2v.w;
        #pragma unroll
        for (int o = 16; o; o >>= 1) p += __shfl_xor_sync(0xffffffffu, p, o);
        if (lane == 0) {
            int k = warp * 8 + kk;
            float x = dt[(size_t)n * KN + k];
            x = fminf(fmaxf(x, 0.0f), 1.0f);
            float xf = x * tscale;
            int   i0 = (int)xf;
            if (i0 > TBL - 2) i0 = TBL - 2;
            float f  = xf - (float)i0;
            float c  = g_tbl[i0] + f * (g_tbl[i0 + 1] - g_tbl[i0]);
            sc[k] = fmaxf(a + p + c + bias, 0.0f);   // relu
        }
    }
    __syncthreads();

    // ---- Softmax over K=32 (warp 0) ----------------------------------------
    if (warp == 0) {
        float s = sc[lane];
        float m = s;
        #pragma unroll
        for (int o = 16; o; o >>= 1)
            m = fmaxf(m, __shfl_xor_sync(0xffffffffu, m, o));
        float e = expf(s - m);
        float sum = e;
        #pragma unroll
        for (int o = 16; o; o >>= 1) sum += __shfl_xor_sync(0xffffffffu, sum, o);
        float w = e / sum;
        sc[lane] = w;
        score_out[(size_t)n * KN + lane] = w;
    }
    __syncthreads();

    // ---- Weighted neighbor sum from registers ------------------------------
    float4 acc = make_float4(0.f, 0.f, 0.f, 0.f);
    #pragma unroll
    for (int kk = 0; kk < 8; kk++) {
        float w = sc[warp * 8 + kk];
        acc.x = fmaf(w, v[kk].x, acc.x);
        acc.y = fmaf(w, v[kk].y, acc.y);
        acc.z = fmaf(w, v[kk].z, acc.z);
        acc.w = fmaf(w, v[kk].w, acc.w);
    }
    *reinterpret_cast<float4*>(&partial[warp][lane * 4]) = acc;
    __syncthreads();

    // Reduce 4 warp-partials per column; thread t owns column t.
    float o0 = partial[0][t] + partial[1][t] + partial[2][t] + partial[3][t];
    out[(size_t)n * D + t] = o0;
}

// ---------------------------------------------------------------------------
// Launch
// ---------------------------------------------------------------------------
extern "C" void kernel_launch(void* const* d_in, const int* in_sizes, int n_in,
                              void* d_out, int out_size) {
    const float* self_vecs = (const float*)d_in[0];  // [N, 128]
    const float* neigh     = (const float*)d_in[1];  // [N, 32, 128]
    const float* dt        = (const float*)d_in[2];  // [N, 32]
    const float* W1        = (const float*)d_in[3];  // [128, 128]
    const float* W2        = (const float*)d_in[4];  // [128, 128]
    const float* W3        = (const float*)d_in[5];  // [1, 128]
    const float* W4        = (const float*)d_in[6];  // [128, 1]
    const float* b4        = (const float*)d_in[7];  // [1]

    float* out   = (float*)d_out;                      // [N, 128] first
    float* score = out + (size_t)N_NODES * D;          // then [N, 32]

    precompute_kernel<<<1 + TBL / 128, 128>>>(W1, W2, W3, W4);
    attn_agg_kernel<<<N_NODES, 128>>>(self_vecs, neigh, dt, b4, out, score);
}